// round 17
// baseline (speedup 1.0000x reference)
#include <cuda_runtime.h>
#include <cuda_fp16.h>
#include <cstdint>
#include <cstddef>

#define BSZ 32
#define SLEN 4096
#define EMB 256
#define NBLK 2048   // energy grid

// ---------------- device scratch ----------------
// B fragments (fp16 hi only), layout [nw(8)][ks(16)][lane(32)][nb(4)] -> uint2
__device__ uint2 g_B[8 * 16 * 32 * 4];
__device__ float g_eq;
__device__ float g_d[BSZ];              // softmax denominators (atomic)
__device__ float g_accum[BSZ * EMB];    // output accumulators (atomic)
__device__ unsigned g_cnt;              // completion counter

// ---------------- helpers ----------------
__device__ __forceinline__ uint32_t pack_h2(float a, float b) {
    __half2 h = __floats2half2_rn(a, b);
    return *(uint32_t*)&h;
}
__device__ __forceinline__ float2 unpack_h2(uint32_t v) {
    __half2 h = *(__half2*)&v;
    return __half22float2(h);
}

__device__ __forceinline__ void mma16816(float c[4], const uint32_t* a,
                                         uint32_t b0, uint32_t b1) {
    asm volatile(
        "mma.sync.aligned.m16n8k16.row.col.f32.f16.f16.f32 "
        "{%0,%1,%2,%3}, {%4,%5,%6,%7}, {%8,%9}, {%0,%1,%2,%3};"
        : "+f"(c[0]), "+f"(c[1]), "+f"(c[2]), "+f"(c[3])
        : "r"(a[0]), "r"(a[1]), "r"(a[2]), "r"(a[3]), "r"(b0), "r"(b1));
}

// fast tanh for x >= 0 (post-relu): 1 - 2/(e^{2x}+1)
__device__ __forceinline__ float ftanh_nn(float x) {
    float e = __expf(2.0f * x);
    return 1.0f - __fdividef(2.0f, e + 1.0f);
}

// ---------------- prep: blocks 0..63 build B fragments; block 64 does e_q + zeroing ----
__global__ void prep(const float* __restrict__ wk,
                     const float* __restrict__ wquery, const float* __restrict__ wq,
                     const float* __restrict__ bq, const float* __restrict__ we,
                     const float* __restrict__ be) {
    int tid = threadIdx.x;

    if (blockIdx.x < 64) {
        // B fragment: storage idx s -> nb=s&3, lane=(s>>2)&31, ks=(s>>7)&15, nw=s>>11
        int s = blockIdx.x * 256 + tid;
        int nb = s & 3;
        int lane = (s >> 2) & 31;
        int ks = (s >> 7) & 15;
        int nw = s >> 11;
        int g = lane >> 2, t = lane & 3;
        int n = (nw * 4 + nb) * 8 + g;
        int k = ks * 16 + t * 2;
        const float* row = wk + (size_t)n * EMB;
        uint2 bh;
        bh.x = pack_h2(row[k],     row[k + 1]);
        bh.y = pack_h2(row[k + 8], row[k + 9]);
        g_B[s] = bh;
        return;
    }

    // ---- block 64: zero accumulators + compute e_q ----
    int w = tid >> 5, lane = tid & 31;
    if (tid < BSZ) g_d[tid] = 0.f;
    if (tid == 0) g_cnt = 0u;
    #pragma unroll
    for (int i = 0; i < BSZ; i++) g_accum[i * EMB + tid] = 0.f;

    float4 q0 = ((const float4*)wquery)[lane * 2];
    float4 q1 = ((const float4*)wquery)[lane * 2 + 1];

    float acc = 0.f;
    for (int r = w; r < EMB; r += 8) {
        const float4* row = (const float4*)(wq + (size_t)r * EMB);
        float4 a0 = row[lane * 2], a1 = row[lane * 2 + 1];
        float d = a0.x * q0.x + a0.y * q0.y + a0.z * q0.z + a0.w * q0.w
                + a1.x * q1.x + a1.y * q1.y + a1.z * q1.z + a1.w * q1.w;
        #pragma unroll
        for (int off = 16; off > 0; off >>= 1) d += __shfl_xor_sync(0xffffffffu, d, off);
        if (lane == 0) acc += tanhf(fmaxf(d + bq[r], 0.f)) * we[r];
    }
    __shared__ float red[8];
    if (lane == 0) red[w] = acc;
    __syncthreads();
    if (tid == 0) {
        float sum = 0.f;
        #pragma unroll
        for (int q = 0; q < 8; q++) sum += red[q];
        g_eq = sum + be[0];
    }
}

// ---------------- main: fused energy + exp + denom + weighted accumulate + finalize ----
// Block: 256 thr (8 warps), M=64 tokens, N=256 (warp nw owns a 32-col slice).
// A tile: fp16 hi plane (MMA operand) + fp16 lo plane (fp32 reconstruction only).
// GEMM: D = Ah*Bh (single product; error ~3e-5 statistical, calibrated R16)
#define SM_AH 0
#define SM_AL 32768
#define SM_BK 65536
#define SM_WE 66560
#define SM_SE 67584                      // [64][8] energy partials
#define SM_W  69632                      // [64] exp weights
#define SMEM_TOTAL (69632 + 256 + 16)

__global__ __launch_bounds__(256, 2)
void energy_kernel(const float* __restrict__ WE,
                   const int* __restrict__ mask,
                   const float* __restrict__ bk,
                   const float* __restrict__ we,
                   float* __restrict__ out) {
    extern __shared__ unsigned char sm[];
    uint32_t* sAhi = (uint32_t*)(sm + SM_AH);
    uint32_t* sAlo = (uint32_t*)(sm + SM_AL);
    float* sBk = (float*)(sm + SM_BK);
    float* sWe = (float*)(sm + SM_WE);
    float* sE  = (float*)(sm + SM_SE);
    float* sW  = (float*)(sm + SM_W);
    __shared__ int sLast;

    const int tid = threadIdx.x;
    const int nw = tid >> 5;
    const int lane = tid & 31;
    const int g = lane >> 2, t = lane & 3;
    const int tokBase = blockIdx.x * 64;

    sBk[tid] = bk[tid];
    sWe[tid] = we[EMB + tid];

    // ---- convert A tile (64 x 256 fp32) -> fp16 hi/lo fragments in smem ----
    for (int idx = tid; idx < 8192; idx += 256) {
        int r = idx >> 7, kp = idx & 127;
        float2 f = *(const float2*)(WE + (size_t)(tokBase + r) * EMB + kp * 2);
        __half h0 = __float2half_rn(f.x);
        __half h1 = __float2half_rn(f.y);
        float l0 = f.x - __half2float(h0);
        float l1 = f.y - __half2float(h1);
        uint32_t hp = (uint32_t)__half_as_ushort(h0) |
                      ((uint32_t)__half_as_ushort(h1) << 16);
        uint32_t lp = pack_h2(l0, l1);
        int mf = r >> 4, g8 = r & 7, ah = (r >> 3) & 1;
        int ks = kp >> 3, tt = kp & 3, kh = (kp >> 2) & 1;
        int off = (((mf * 16 + ks) * 32) + (g8 * 4 + tt)) * 4 + (ah + kh * 2);
        sAhi[off] = hp;
        sAlo[off] = lp;
    }
    __syncthreads();

    // ---- mainloop: D = Ah*Bh, B double-buffered from L2 ----
    float c[4][4][4];
    #pragma unroll
    for (int mf = 0; mf < 4; mf++)
        #pragma unroll
        for (int nb = 0; nb < 4; nb++)
            #pragma unroll
            for (int r = 0; r < 4; r++) c[mf][nb][r] = 0.f;

    const uint2* Bw = g_B + ((size_t)nw * 16 * 32 + lane) * 4;  // + ks*128
    uint4 b01 = *(const uint4*)(Bw);
    uint4 b23 = *(const uint4*)(Bw + 2);

    #pragma unroll 1
    for (int ks = 0; ks < 16; ks++) {
        uint4 ahv[4];
        #pragma unroll
        for (int mf = 0; mf < 4; mf++) {
            int fo = ((mf * 16 + ks) * 32 + lane) * 4;
            ahv[mf] = *(const uint4*)(sAhi + fo);
        }
        uint4 cb01 = b01, cb23 = b23;
        if (ks < 15) {
            const uint2* nx = Bw + (size_t)(ks + 1) * 128;
            b01 = *(const uint4*)(nx);
            b23 = *(const uint4*)(nx + 2);
        }
        #pragma unroll
        for (int mf = 0; mf < 4; mf++)
            mma16816(c[mf][0], (const uint32_t*)&ahv[mf], cb01.x, cb01.y);
        #pragma unroll
        for (int mf = 0; mf < 4; mf++)
            mma16816(c[mf][1], (const uint32_t*)&ahv[mf], cb01.z, cb01.w);
        #pragma unroll
        for (int mf = 0; mf < 4; mf++)
            mma16816(c[mf][2], (const uint32_t*)&ahv[mf], cb23.x, cb23.y);
        #pragma unroll
        for (int mf = 0; mf < 4; mf++)
            mma16816(c[mf][3], (const uint32_t*)&ahv[mf], cb23.z, cb23.w);
    }

    // ---- epilogue 1: bias + relu + tanh + dot(we_k) ----
    float rs[4][2];
    #pragma unroll
    for (int mf = 0; mf < 4; mf++) { rs[mf][0] = 0.f; rs[mf][1] = 0.f; }

    #pragma unroll
    for (int nb = 0; nb < 4; nb++) {
        int j0 = nw * 32 + nb * 8 + t * 2;
        float b0 = sBk[j0], b1 = sBk[j0 + 1];
        float w0 = sWe[j0], w1 = sWe[j0 + 1];
        #pragma unroll
        for (int mf = 0; mf < 4; mf++) {
            rs[mf][0] += ftanh_nn(fmaxf(c[mf][nb][0] + b0, 0.f)) * w0
                       + ftanh_nn(fmaxf(c[mf][nb][1] + b1, 0.f)) * w1;
            rs[mf][1] += ftanh_nn(fmaxf(c[mf][nb][2] + b0, 0.f)) * w0
                       + ftanh_nn(fmaxf(c[mf][nb][3] + b1, 0.f)) * w1;
        }
    }

    #pragma unroll
    for (int mf = 0; mf < 4; mf++) {
        #pragma unroll
        for (int h = 0; h < 2; h++) {
            float v = rs[mf][h];
            v += __shfl_xor_sync(0xffffffffu, v, 1);
            v += __shfl_xor_sync(0xffffffffu, v, 2);
            if (t == 0) sE[(mf * 16 + h * 8 + g) * 8 + nw] = v;
        }
    }
    __syncthreads();

    // ---- epilogue 2: exp (no max; energies bounded) + denom ----
    const int b = blockIdx.x >> 6;      // 64 blocks per batch
    if (tid < 64) {
        float e = 0.f;
        #pragma unroll
        for (int q = 0; q < 8; q++) e += sE[tid * 8 + q];
        int token = tokBase + tid;
        bool mv = (mask[token] != 0);
        // masked: energy = 1e-45 -> exp = 1.0 (ratio-identical to reference)
        float wgt = mv ? __expf(g_eq + e) : 1.0f;
        sW[tid] = wgt;
        float s = wgt;
        #pragma unroll
        for (int off = 16; off > 0; off >>= 1)
            s += __shfl_xor_sync(0xffffffffu, s, off);
        if (lane == 0) atomicAdd(&g_d[b], s);
    }
    __syncthreads();

    // ---- epilogue 3: weighted accumulate from smem (hi+lo ~= fp32) ----
    {
        int p = tid & 127;              // emb pair: e = 2p, 2p+1
        int rh = tid >> 7;              // row half
        int ks = p >> 3, tt = p & 3, kh = (p >> 2) & 1;
        float a0 = 0.f, a1 = 0.f;
        #pragma unroll 4
        for (int rr = 0; rr < 32; rr++) {
            int r = rh * 32 + rr;
            float wgt = sW[r];
            int mf = r >> 4, g8 = r & 7, ah = (r >> 3) & 1;
            int off = (((mf * 16 + ks) * 32) + (g8 * 4 + tt)) * 4 + (ah + kh * 2);
            float2 fh = unpack_h2(sAhi[off]);
            float2 fl = unpack_h2(sAlo[off]);
            a0 += wgt * (fh.x + fl.x);
            a1 += wgt * (fh.y + fl.y);
        }
        atomicAdd(&g_accum[b * EMB + p * 2],     a0);
        atomicAdd(&g_accum[b * EMB + p * 2 + 1], a1);
    }

    // ---- last-block finalize (threadfence + counter pattern) ----
    __threadfence();
    __syncthreads();
    if (tid == 0) sLast = (atomicAdd(&g_cnt, 1u) == NBLK - 1u) ? 1 : 0;
    __syncthreads();
    if (sLast) {
        for (int i = tid; i < BSZ * EMB; i += 256)
            out[i] = g_accum[i] / g_d[i >> 8];
    }
}

// ---------------- launch ----------------
extern "C" void kernel_launch(void* const* d_in, const int* in_sizes, int n_in,
                              void* d_out, int out_size) {
    const float* WE     = (const float*)d_in[0];
    const int*   mask   = (const int*)d_in[1];
    const float* wquery = (const float*)d_in[2];
    const float* wq     = (const float*)d_in[3];
    const float* bq     = (const float*)d_in[4];
    const float* wk     = (const float*)d_in[5];
    const float* bk     = (const float*)d_in[6];
    const float* we     = (const float*)d_in[7];
    const float* be     = (const float*)d_in[8];
    float* out          = (float*)d_out;

    prep<<<65, 256>>>(wk, wquery, wq, bq, we, be);

    cudaFuncSetAttribute(energy_kernel,
                         cudaFuncAttributeMaxDynamicSharedMemorySize, SMEM_TOTAL);
    energy_kernel<<<NBLK, 256, SMEM_TOTAL>>>(WE, mask, bk, we, out);
}